// round 13
// baseline (speedup 1.0000x reference)
#include <cuda_runtime.h>

#define TILE 16
#define NBOX 64
#define TILES_PER_IMG 134   // 100 (L0 10x10) + 25 (L1 5x5) + 9 (L2 3x3)
#define MAX_B 64
#define NPART_MAX (TILES_PER_IMG * MAX_B)

#define NTAB 2048
#define TAB_MAX 18.0f       // az range covered by LUT; beyond: l1~0, sigma~1

// LUT for l1(a)=log(1+exp(-a)) and s(a)=sigmoid(a), a in [0,18].
// Entry i covers [i*h,(i+1)*h): value + delta for linear interpolation.
// Filled by lut_init_kernel each run (idempotent, deterministic).
struct __align__(16) LutE { float l1, dl1, s, ds; };
__device__ LutE g_lut[NTAB];

__global__ void lut_init_kernel() {
    const int i = blockIdx.x * blockDim.x + threadIdx.x;
    if (i >= NTAB) return;
    const float h = TAB_MAX / (float)NTAB;
    const float a0 = i * h, a1 = (i + 1) * h;
    // Full-precision math here (runs once over 2048 entries; cost ~0).
    const float e0 = expf(-a0), e1 = expf(-a1);
    const float l10 = log1pf(e0), l11 = log1pf(e1);
    const float s0 = 1.0f / (1.0f + e0), s1 = 1.0f / (1.0f + e1);
    LutE v;
    v.l1 = l10; v.dl1 = l11 - l10;
    v.s  = s0;  v.ds  = s1 - s0;
    g_lut[i] = v;
}

// Per-block partial sums: [slot*3 + {0:cls,1:reg,2:npos}]
__device__ double g_partial[NPART_MAX * 3];
__device__ unsigned int g_ticket;   // zero-init; reset by last block each run

__global__ __launch_bounds__(256) void fcos_fused_kernel(
    const float* __restrict__ cls0, const float* __restrict__ cls1,
    const float* __restrict__ cls2,
    const float* __restrict__ reg0, const float* __restrict__ reg1,
    const float* __restrict__ reg2,
    const float* __restrict__ gt,
    float* __restrict__ out, int B, int nblocks)
{
    __shared__ float s_gt[NBOX * 4];
    __shared__ float cx0[NBOX], cy0[NBOX], cx1[NBOX], cy1[NBOX], car[NBOX];
    __shared__ int s_ncand;
    __shared__ float s_red[3 * 8];
    __shared__ bool s_is_last;
    __shared__ double f0[256], f1[256], f2[256];

    const int bid = blockIdx.x;
    const int tid = threadIdx.x;
    const int b = bid / TILES_PER_IMG;
    int r = bid - b * TILES_PER_IMG;

    // Decode level + tile coords + per-level constants.
    const float* cls; const float* reg;
    int H, W, tx0, ty0;
    float stride, low, high;
    if (r < 100) {
        cls = cls0; reg = reg0; H = 160; W = 160;
        stride = 4.f; low = -1.f; high = 64.f;
        ty0 = r / 10; tx0 = r - ty0 * 10;
    } else if (r < 125) {
        r -= 100;
        cls = cls1; reg = reg1; H = 80; W = 80;
        stride = 8.f; low = 64.f; high = 128.f;
        ty0 = r / 5; tx0 = r - ty0 * 5;
    } else {
        r -= 125;
        cls = cls2; reg = reg2; H = 40; W = 40;
        stride = 16.f; low = 128.f; high = 99999.f;
        ty0 = r / 3; tx0 = r - ty0 * 3;
    }

    // Load this image's 64 boxes (256 floats) coalesced.
    s_gt[tid] = gt[b * NBOX * 4 + tid];
    __syncthreads();

    const int w0 = tx0 * TILE;
    const int h0 = ty0 * TILE;
    const float x_min = (w0 + 0.5f) * stride;
    const float x_max = (min(w0 + TILE - 1, W - 1) + 0.5f) * stride;
    const float y_min = (h0 + 0.5f) * stride;
    const float y_max = (min(h0 + TILE - 1, H - 1) + 0.5f) * stride;

    // Warp 0: ordered compaction of candidate boxes for this tile.
    // For a point strictly inside a box: l+r = bw, t+b = bh, hence
    //   max(bw,bh)/2 <= max(l,t,r,b) < max(bw,bh).
    // So in_lvl requires mwh > low and mwh/2 < high; in_box requires
    // tile-bbox overlap. Necessary conditions => kept set is a superset.
    if (tid < 32) {
        int base = 0;
        #pragma unroll
        for (int chunk = 0; chunk < 2; ++chunk) {
            const int m = tid + chunk * 32;
            const float bx0 = s_gt[m * 4 + 0];
            const float by0 = s_gt[m * 4 + 1];
            const float bx1 = s_gt[m * 4 + 2];
            const float by1 = s_gt[m * 4 + 3];
            const float bw = bx1 - bx0, bh = by1 - by0;
            const float mwh = fmaxf(bw, bh);
            const bool keep = (bx0 < x_max) && (bx1 > x_min) &&
                              (by0 < y_max) && (by1 > y_min) &&
                              (mwh > low) && (0.5f * mwh < high);
            const unsigned mask = __ballot_sync(0xffffffffu, keep);
            if (keep) {
                const int pos = base + __popc(mask & ((1u << tid) - 1u));
                cx0[pos] = bx0; cy0[pos] = by0;
                cx1[pos] = bx1; cy1[pos] = by1;
                car[pos] = bw * bh;
            }
            base += __popc(mask);
        }
        if (tid == 0) s_ncand = base;
    }
    __syncthreads();

    const int tx = tid & (TILE - 1);
    const int ty = tid >> 4;
    const int w = w0 + tx;
    const int h = h0 + ty;

    float cls_c = 0.f, reg_c = 0.f, np_c = 0.f;

    if (w < W && h < H) {
        const float x = (w + 0.5f) * stride;
        const float y = (h + 0.5f) * stride;

        // Issue all 5 global loads up front so their latency overlaps the
        // candidate scan below.
        const int HW = H * W;
        const int pidx = h * W + w;
        const float z = cls[(size_t)b * HW + pidx];
        const float* rb = reg + (size_t)b * 4 * HW + pidx;
        const float pl = rb[0];
        const float pt = rb[HW];
        const float pr = rb[2 * HW];
        const float pb = rb[3 * HW];

        // LUT fetch for the varifocal transcendentals (replaces EX2/LG2/RCP
        // MUFU ops -> 1 L1-resident LDG.128 + 2 FMA interpolation).
        const float az = fabsf(z);
        const float u = fminf(az * ((float)NTAB / TAB_MAX), (float)NTAB - 1.001f);
        const int ii = (int)u;
        const float fr = u - (float)ii;
        const float4 tv = __ldg((const float4*)&g_lut[ii]);
        const float l1 = fmaf(fr, tv.y, tv.x);        // log(1+e^{-az})
        const float sp = fmaf(fr, tv.w, tv.z);        // sigmoid(az)

        const int nc = s_ncand;
        float best = __int_as_float(0x7f800000);  // +inf
        int bslot = -1;
        // Candidates preserve original box-index order; strict < keeps the
        // first minimum, matching jnp.argmin tie-breaking.
        for (int c = 0; c < nc; ++c) {
            const float l = x - cx0[c];
            const float t = y - cy0[c];
            const float rr = cx1[c] - x;
            const float bo = cy1[c] - y;
            const float mn = fminf(fminf(l, t), fminf(rr, bo));
            const float mx = fmaxf(fmaxf(l, t), fmaxf(rr, bo));
            const bool ok = (mn > 0.f) & (mx > low) & (mx < high);
            const float a = car[c];
            if (ok && a < best) { best = a; bslot = c; }
        }

        float gt_iou = 0.f;
        if (bslot >= 0) {
            const float tl = x - cx0[bslot];
            const float tt = y - cy0[bslot];
            const float tr = cx1[bslot] - x;
            const float tb = cy1[bslot] - y;
            const float w_i = fminf(pl, tl) + fminf(pr, tr);
            const float h_i = fminf(pt, tt) + fminf(pb, tb);
            const float a_i = fmaxf(w_i, 0.f) * fmaxf(h_i, 0.f);
            const float a_p = (pl + pr) * (pt + pb);
            const float a_t = (tl + tr) * (tt + tb);
            const float a_u = a_p + a_t - a_i + 1e-7f;
            const float iou = __fdividef(a_i, a_u);
            gt_iou = fminf(fmaxf(iou, 0.f), 1.f);
            const float w_e = fmaxf(pl, tl) + fmaxf(pr, tr);
            const float h_e = fmaxf(pt, tt) + fmaxf(pb, tb);
            const float a_e = fmaxf(w_e, 0.f) * fmaxf(h_e, 0.f) + 1e-7f;
            const float giou = iou - __fdividef(a_e - a_u, a_e);
            reg_c = 1.f - giou;
            np_c = 1.f;
        }

        // Varifocal loss from LUT values:
        //   log_p  = min(z,0)  - l1
        //   log_np = min(-z,0) - l1
        //   p = sigmoid(z) = (z>=0) ? sp : 1-sp
        const float log_p  = fminf(z, 0.f) - l1;
        const float log_np = fminf(-z, 0.f) - l1;
        const float p = (z >= 0.f) ? sp : (1.f - sp);
        if (gt_iou > 0.f)
            cls_c = -gt_iou * (gt_iou * log_p + (1.f - gt_iou) * log_np);
        else
            cls_c = -0.75f * p * p * log_np;
    }

    // Block reduction: warp shuffle -> shared -> thread 0 writes partial slot.
    const unsigned fm = 0xffffffffu;
    #pragma unroll
    for (int o = 16; o > 0; o >>= 1) {
        cls_c += __shfl_down_sync(fm, cls_c, o);
        reg_c += __shfl_down_sync(fm, reg_c, o);
        np_c  += __shfl_down_sync(fm, np_c, o);
    }
    const int lane = tid & 31;
    const int wid = tid >> 5;
    if (lane == 0) {
        s_red[wid]      = cls_c;
        s_red[8 + wid]  = reg_c;
        s_red[16 + wid] = np_c;
    }
    __syncthreads();
    if (tid == 0) {
        float a = 0.f, bb = 0.f, cc = 0.f;
        #pragma unroll
        for (int i = 0; i < 8; ++i) {
            a  += s_red[i];
            bb += s_red[8 + i];
            cc += s_red[16 + i];
        }
        g_partial[bid * 3 + 0] = (double)a;
        g_partial[bid * 3 + 1] = (double)bb;
        g_partial[bid * 3 + 2] = (double)cc;
        __threadfence();
        const unsigned ticket = atomicAdd(&g_ticket, 1u);
        s_is_last = (ticket == (unsigned)(nblocks - 1));
    }
    __syncthreads();

    // Last-arriving block performs the deterministic final reduction.
    if (s_is_last) {
        __threadfence();  // make all partials visible
        double a = 0.0, bb = 0.0, cc = 0.0;
        for (int i = tid; i < nblocks; i += 256) {
            a  += g_partial[i * 3 + 0];
            bb += g_partial[i * 3 + 1];
            cc += g_partial[i * 3 + 2];
        }
        f0[tid] = a; f1[tid] = bb; f2[tid] = cc;
        __syncthreads();
        for (int o = 128; o > 0; o >>= 1) {
            if (tid < o) {
                f0[tid] += f0[tid + o];
                f1[tid] += f1[tid + o];
                f2[tid] += f2[tid + o];
            }
            __syncthreads();
        }
        if (tid == 0) {
            const double clsS = f0[0], regS = f1[0], npS = f2[0];
            const double navg = fmax(1.0, npS / (double)B);
            out[0] = (float)((clsS + regS) / navg);
            out[1] = (float)(clsS / navg);
            out[2] = (float)(regS / navg);
            g_ticket = 0;  // reset for next graph replay (deterministic)
        }
    }
}

extern "C" void kernel_launch(void* const* d_in, const int* in_sizes, int n_in,
                              void* d_out, int out_size) {
    const float* cls0 = (const float*)d_in[0];  // (B,1,160,160)
    const float* cls1 = (const float*)d_in[1];  // (B,1,80,80)
    const float* cls2 = (const float*)d_in[2];  // (B,1,40,40)
    const float* reg0 = (const float*)d_in[3];  // (B,4,160,160)
    const float* reg1 = (const float*)d_in[4];  // (B,4,80,80)
    const float* reg2 = (const float*)d_in[5];  // (B,4,40,40)
    const float* gt   = (const float*)d_in[6];  // (B,64,4)
    float* out = (float*)d_out;

    int B = in_sizes[6] / (NBOX * 4);
    if (B > MAX_B) B = MAX_B;
    const int nblocks = B * TILES_PER_IMG;

    lut_init_kernel<<<(NTAB + 255) / 256, 256>>>();
    fcos_fused_kernel<<<nblocks, 256>>>(cls0, cls1, cls2, reg0, reg1, reg2,
                                        gt, out, B, nblocks);
}

// round 14
// speedup vs baseline: 1.1780x; 1.1780x over previous
#include <cuda_runtime.h>

#define TILE 16
#define NBOX 64
#define TILES_PER_IMG 134   // 100 (L0 10x10) + 25 (L1 5x5) + 9 (L2 3x3)
#define JOBS_PER_IMG 67     // 2 tiles per job
#define MAX_B 64
#define NJOB_MAX (JOBS_PER_IMG * MAX_B)

// Per-block partial sums, separate contiguous arrays (vector-friendly tail).
__device__ double g_p0[NJOB_MAX];
__device__ double g_p1[NJOB_MAX];
__device__ double g_p2[NJOB_MAX];
__device__ unsigned int g_ticket;   // zero-init; reset by last block each run

__global__ __launch_bounds__(256) void fcos_fused_kernel(
    const float* __restrict__ cls0, const float* __restrict__ cls1,
    const float* __restrict__ cls2,
    const float* __restrict__ reg0, const float* __restrict__ reg1,
    const float* __restrict__ reg2,
    const float* __restrict__ gt,
    float* __restrict__ out, int B, int nblocks)
{
    __shared__ float s_gt[NBOX * 4];
    __shared__ float cx0[NBOX], cy0[NBOX], cx1[NBOX], cy1[NBOX], car[NBOX];
    __shared__ int s_ncand;
    __shared__ float s_red[3 * 8];
    __shared__ bool s_is_last;
    __shared__ double s_fin[3 * 8];

    const int bid = blockIdx.x;
    const int tid = threadIdx.x;
    const int b = bid / JOBS_PER_IMG;
    const int job = bid - b * JOBS_PER_IMG;

    // Load this image's 64 boxes (256 floats) coalesced — once for 2 tiles.
    s_gt[tid] = gt[b * NBOX * 4 + tid];

    float cls_c = 0.f, reg_c = 0.f, np_c = 0.f;

    #pragma unroll
    for (int half = 0; half < 2; ++half) {
        int r = job * 2 + half;    // tile id 0..133

        // Decode level + tile coords + per-level constants.
        const float* cls; const float* reg;
        int H, W, tx0, ty0;
        float stride, low, high;
        if (r < 100) {
            cls = cls0; reg = reg0; H = 160; W = 160;
            stride = 4.f; low = -1.f; high = 64.f;
            ty0 = r / 10; tx0 = r - ty0 * 10;
        } else if (r < 125) {
            r -= 100;
            cls = cls1; reg = reg1; H = 80; W = 80;
            stride = 8.f; low = 64.f; high = 128.f;
            ty0 = r / 5; tx0 = r - ty0 * 5;
        } else {
            r -= 125;
            cls = cls2; reg = reg2; H = 40; W = 40;
            stride = 16.f; low = 128.f; high = 99999.f;
            ty0 = r / 3; tx0 = r - ty0 * 3;
        }

        const int w0 = tx0 * TILE;
        const int h0 = ty0 * TILE;
        const float x_min = (w0 + 0.5f) * stride;
        const float x_max = (min(w0 + TILE - 1, W - 1) + 0.5f) * stride;
        const float y_min = (h0 + 0.5f) * stride;
        const float y_max = (min(h0 + TILE - 1, H - 1) + 0.5f) * stride;

        // Barrier: half 0 -> s_gt visible; half 1 -> prior tile done reading
        // the candidate arrays before warp 0 overwrites them.
        __syncthreads();

        // Warp 0: ordered compaction of candidate boxes for this tile.
        // Point strictly inside box => l+r=bw, t+b=bh =>
        //   max(bw,bh)/2 <= max(l,t,r,b) < max(bw,bh);
        // so keep requires tile-bbox overlap, mwh > low, mwh/2 < high.
        if (tid < 32) {
            int base = 0;
            #pragma unroll
            for (int chunk = 0; chunk < 2; ++chunk) {
                const int m = tid + chunk * 32;
                const float bx0 = s_gt[m * 4 + 0];
                const float by0 = s_gt[m * 4 + 1];
                const float bx1 = s_gt[m * 4 + 2];
                const float by1 = s_gt[m * 4 + 3];
                const float bw = bx1 - bx0, bh = by1 - by0;
                const float mwh = fmaxf(bw, bh);
                const bool keep = (bx0 < x_max) && (bx1 > x_min) &&
                                  (by0 < y_max) && (by1 > y_min) &&
                                  (mwh > low) && (0.5f * mwh < high);
                const unsigned mask = __ballot_sync(0xffffffffu, keep);
                if (keep) {
                    const int pos = base + __popc(mask & ((1u << tid) - 1u));
                    cx0[pos] = bx0; cy0[pos] = by0;
                    cx1[pos] = bx1; cy1[pos] = by1;
                    car[pos] = bw * bh;
                }
                base += __popc(mask);
            }
            if (tid == 0) s_ncand = base;
        }
        __syncthreads();

        const int tx = tid & (TILE - 1);
        const int ty = tid >> 4;
        const int w = w0 + tx;
        const int h = h0 + ty;

        if (w < W && h < H) {
            const float x = (w + 0.5f) * stride;
            const float y = (h + 0.5f) * stride;

            // Issue all 5 global loads up front so their latency overlaps
            // the candidate scan below.
            const int HW = H * W;
            const int pidx = h * W + w;
            const float z = cls[(size_t)b * HW + pidx];
            const float* rb = reg + (size_t)b * 4 * HW + pidx;
            const float pl = rb[0];
            const float pt = rb[HW];
            const float pr = rb[2 * HW];
            const float pb = rb[3 * HW];

            const int nc = s_ncand;
            float best = __int_as_float(0x7f800000);  // +inf
            int bslot = -1;
            // Candidates preserve original box-index order; strict < keeps
            // the first minimum, matching jnp.argmin tie-breaking.
            for (int c = 0; c < nc; ++c) {
                const float l = x - cx0[c];
                const float t = y - cy0[c];
                const float rr = cx1[c] - x;
                const float bo = cy1[c] - y;
                const float mn = fminf(fminf(l, t), fminf(rr, bo));
                const float mx = fmaxf(fmaxf(l, t), fmaxf(rr, bo));
                const bool ok = (mn > 0.f) & (mx > low) & (mx < high);
                const float a = car[c];
                if (ok && a < best) { best = a; bslot = c; }
            }

            float gt_iou = 0.f;
            if (bslot >= 0) {
                const float tl = x - cx0[bslot];
                const float tt = y - cy0[bslot];
                const float tr = cx1[bslot] - x;
                const float tb = cy1[bslot] - y;
                const float w_i = fminf(pl, tl) + fminf(pr, tr);
                const float h_i = fminf(pt, tt) + fminf(pb, tb);
                const float a_i = fmaxf(w_i, 0.f) * fmaxf(h_i, 0.f);
                const float a_p = (pl + pr) * (pt + pb);
                const float a_t = (tl + tr) * (tt + tb);
                const float a_u = a_p + a_t - a_i + 1e-7f;
                const float iou = __fdividef(a_i, a_u);
                gt_iou = fminf(fmaxf(iou, 0.f), 1.f);
                const float w_e = fmaxf(pl, tl) + fmaxf(pr, tr);
                const float h_e = fmaxf(pt, tt) + fmaxf(pb, tb);
                const float a_e = fmaxf(w_e, 0.f) * fmaxf(h_e, 0.f) + 1e-7f;
                const float giou = iou - __fdividef(a_e - a_u, a_e);
                reg_c += 1.f - giou;
                np_c += 1.f;
            }

            // Varifocal loss, fast-math stable log-sigmoid:
            //   log_p  = min(z,0)  - log(1+exp(-|z|))
            //   log_np = min(-z,0) - log(1+exp(-|z|))
            const float az = fabsf(z);
            const float e = __expf(-az);
            const float l1 = __logf(1.f + e);
            const float log_p  = fminf(z, 0.f) - l1;
            const float log_np = fminf(-z, 0.f) - l1;
            const float inv1pe = __fdividef(1.f, 1.f + e);
            const float p = (z >= 0.f ? 1.f : e) * inv1pe;
            if (gt_iou > 0.f)
                cls_c += -gt_iou * (gt_iou * log_p + (1.f - gt_iou) * log_np);
            else
                cls_c += -0.75f * p * p * log_np;
        }
    }

    // Block reduction: warp shuffle -> shared -> thread 0 writes partial slot.
    const unsigned fm = 0xffffffffu;
    #pragma unroll
    for (int o = 16; o > 0; o >>= 1) {
        cls_c += __shfl_down_sync(fm, cls_c, o);
        reg_c += __shfl_down_sync(fm, reg_c, o);
        np_c  += __shfl_down_sync(fm, np_c, o);
    }
    const int lane = tid & 31;
    const int wid = tid >> 5;
    if (lane == 0) {
        s_red[wid]      = cls_c;
        s_red[8 + wid]  = reg_c;
        s_red[16 + wid] = np_c;
    }
    __syncthreads();
    if (tid == 0) {
        float a = 0.f, bb = 0.f, cc = 0.f;
        #pragma unroll
        for (int i = 0; i < 8; ++i) {
            a  += s_red[i];
            bb += s_red[8 + i];
            cc += s_red[16 + i];
        }
        g_p0[bid] = (double)a;
        g_p1[bid] = (double)bb;
        g_p2[bid] = (double)cc;
        __threadfence();
        const unsigned ticket = atomicAdd(&g_ticket, 1u);
        s_is_last = (ticket == (unsigned)(nblocks - 1));
    }
    __syncthreads();

    // Last-arriving block performs the deterministic final reduction.
    if (s_is_last) {
        __threadfence();  // make all partials visible
        double a = 0.0, bb = 0.0, cc = 0.0;
        for (int i = tid; i < nblocks; i += 256) {
            a  += g_p0[i];
            bb += g_p1[i];
            cc += g_p2[i];
        }
        // Warp shuffle tree on doubles (fixed order -> deterministic).
        #pragma unroll
        for (int o = 16; o > 0; o >>= 1) {
            a  += __shfl_down_sync(fm, a, o);
            bb += __shfl_down_sync(fm, bb, o);
            cc += __shfl_down_sync(fm, cc, o);
        }
        if (lane == 0) {
            s_fin[wid]      = a;
            s_fin[8 + wid]  = bb;
            s_fin[16 + wid] = cc;
        }
        __syncthreads();
        if (tid == 0) {
            double fa = 0.0, fb = 0.0, fc = 0.0;
            #pragma unroll
            for (int i = 0; i < 8; ++i) {
                fa += s_fin[i];
                fb += s_fin[8 + i];
                fc += s_fin[16 + i];
            }
            const double navg = fmax(1.0, fc / (double)B);
            out[0] = (float)((fa + fb) / navg);
            out[1] = (float)(fa / navg);
            out[2] = (float)(fb / navg);
            g_ticket = 0;  // reset for next graph replay (deterministic)
        }
    }
}

extern "C" void kernel_launch(void* const* d_in, const int* in_sizes, int n_in,
                              void* d_out, int out_size) {
    const float* cls0 = (const float*)d_in[0];  // (B,1,160,160)
    const float* cls1 = (const float*)d_in[1];  // (B,1,80,80)
    const float* cls2 = (const float*)d_in[2];  // (B,1,40,40)
    const float* reg0 = (const float*)d_in[3];  // (B,4,160,160)
    const float* reg1 = (const float*)d_in[4];  // (B,4,80,80)
    const float* reg2 = (const float*)d_in[5];  // (B,4,40,40)
    const float* gt   = (const float*)d_in[6];  // (B,64,4)
    float* out = (float*)d_out;

    int B = in_sizes[6] / (NBOX * 4);
    if (B > MAX_B) B = MAX_B;
    const int nblocks = B * JOBS_PER_IMG;   // 1072 for B=16 -> single wave

    fcos_fused_kernel<<<nblocks, 256>>>(cls0, cls1, cls2, reg0, reg1, reg2,
                                        gt, out, B, nblocks);
}

// round 15
// speedup vs baseline: 1.2000x; 1.0187x over previous
#include <cuda_runtime.h>

#define TILE 16
#define JOBS_PER_IMG 67     // 2 tiles per block; 134 tiles/image
#define MAX_B 64
#define NJOB_MAX (JOBS_PER_IMG * MAX_B)
#define FULL 0xffffffffu

// Per-block partial sums, contiguous arrays.
__device__ double g_p0[NJOB_MAX];
__device__ double g_p1[NJOB_MAX];
__device__ double g_p2[NJOB_MAX];
__device__ unsigned int g_ticket;   // zero-init; reset by last block each run

__global__ __launch_bounds__(256) void fcos_fused_kernel(
    const float* __restrict__ cls0, const float* __restrict__ cls1,
    const float* __restrict__ cls2,
    const float* __restrict__ reg0, const float* __restrict__ reg1,
    const float* __restrict__ reg2,
    const float4* __restrict__ gt4,
    float* __restrict__ out, int B, int nblocks)
{
    __shared__ float s_red[3 * 8];
    __shared__ double s_fin[3 * 8];
    __shared__ bool s_is_last;

    const int bid = blockIdx.x;
    const int tid = threadIdx.x;
    const int wid = tid >> 5;
    const int lane = tid & 31;
    const int b = bid / JOBS_PER_IMG;
    const int job = bid - b * JOBS_PER_IMG;

    // Each lane holds 2 boxes in registers (coalesced float4 loads).
    const float4 bxA = gt4[b * 64 + lane];
    const float4 bxB = gt4[b * 64 + 32 + lane];
    const float mwhA = fmaxf(bxA.z - bxA.x, bxA.w - bxA.y);
    const float mwhB = fmaxf(bxB.z - bxB.x, bxB.w - bxB.y);

    float cls_c = 0.f, reg_c = 0.f, np_c = 0.f;

    #pragma unroll
    for (int half = 0; half < 2; ++half) {
        int r = job * 2 + half;    // tile id 0..133

        // Decode level + tile coords + per-level constants.
        const float* cls; const float* reg;
        int H, W, tx0, ty0;
        float stride, low, high;
        if (r < 100) {
            cls = cls0; reg = reg0; H = 160; W = 160;
            stride = 4.f; low = -1.f; high = 64.f;
            ty0 = r / 10; tx0 = r - ty0 * 10;
        } else if (r < 125) {
            r -= 100;
            cls = cls1; reg = reg1; H = 80; W = 80;
            stride = 8.f; low = 64.f; high = 128.f;
            ty0 = r / 5; tx0 = r - ty0 * 5;
        } else {
            r -= 125;
            cls = cls2; reg = reg2; H = 40; W = 40;
            stride = 16.f; low = 128.f; high = 99999.f;
            ty0 = r / 3; tx0 = r - ty0 * 3;
        }

        const int w0 = tx0 * TILE;
        const int rowb = ty0 * TILE + 2 * wid;   // this warp's 2-row strip
        if (rowb >= H) continue;                 // warp-uniform (L2 edge tiles)

        const int lx = lane & 15;
        const int ly = lane >> 4;
        const int w = w0 + lx;
        const int h = rowb + ly;
        const bool valid = (w < W) & (h < H);

        // Warp-strip bbox over point centers.
        const float x_min = (w0 + 0.5f) * stride;
        const float x_max = ((float)min(w0 + TILE - 1, W - 1) + 0.5f) * stride;
        const float y_min = ((float)rowb + 0.5f) * stride;
        const float y_max = ((float)min(rowb + 1, H - 1) + 0.5f) * stride;

        // Candidate masks (necessary conditions: a strictly-inside point has
        // max(bw,bh)/2 <= max(l,t,r,b) < max(bw,bh), plus strip-bbox overlap).
        const bool keepA = (bxA.x < x_max) && (bxA.z > x_min) &&
                           (bxA.y < y_max) && (bxA.w > y_min) &&
                           (mwhA > low) && (0.5f * mwhA < high);
        const bool keepB = (bxB.x < x_max) && (bxB.z > x_min) &&
                           (bxB.y < y_max) && (bxB.w > y_min) &&
                           (mwhB > low) && (0.5f * mwhB < high);
        const unsigned m0 = __ballot_sync(FULL, keepA);
        const unsigned m1 = __ballot_sync(FULL, keepB);

        const float x = (w + 0.5f) * stride;
        const float y = (h + 0.5f) * stride;

        // Hoist the 5 global loads so latency overlaps the shfl scan.
        const int HW = H * W;
        const int pidx = h * W + w;
        float z = 0.f, pl = 0.f, pt = 0.f, pr = 0.f, pb = 0.f;
        if (valid) {
            z = cls[(size_t)b * HW + pidx];
            const float* rb = reg + (size_t)b * 4 * HW + pidx;
            pl = rb[0];
            pt = rb[HW];
            pr = rb[2 * HW];
            pb = rb[3 * HW];
        }

        // Scan candidates in box-index order (LSB->MSB, chunk A then B):
        // strict < keeps the first minimum => jnp.argmin tie-breaking.
        float best = __int_as_float(0x7f800000);  // +inf
        float tl = 0.f, tt = 0.f, tr = 0.f, tb = 0.f;

        unsigned mm = m0;
        while (mm) {
            const int c = __ffs(mm) - 1; mm &= mm - 1;
            const float qx0 = __shfl_sync(FULL, bxA.x, c);
            const float qy0 = __shfl_sync(FULL, bxA.y, c);
            const float qx1 = __shfl_sync(FULL, bxA.z, c);
            const float qy1 = __shfl_sync(FULL, bxA.w, c);
            const float l  = x - qx0;
            const float t  = y - qy0;
            const float rr = qx1 - x;
            const float bo = qy1 - y;
            const float mn = fminf(fminf(l, t), fminf(rr, bo));
            const float mx = fmaxf(fmaxf(l, t), fmaxf(rr, bo));
            const float ar = (qx1 - qx0) * (qy1 - qy0);
            if ((mn > 0.f) & (mx > low) & (mx < high) && ar < best) {
                best = ar; tl = l; tt = t; tr = rr; tb = bo;
            }
        }
        mm = m1;
        while (mm) {
            const int c = __ffs(mm) - 1; mm &= mm - 1;
            const float qx0 = __shfl_sync(FULL, bxB.x, c);
            const float qy0 = __shfl_sync(FULL, bxB.y, c);
            const float qx1 = __shfl_sync(FULL, bxB.z, c);
            const float qy1 = __shfl_sync(FULL, bxB.w, c);
            const float l  = x - qx0;
            const float t  = y - qy0;
            const float rr = qx1 - x;
            const float bo = qy1 - y;
            const float mn = fminf(fminf(l, t), fminf(rr, bo));
            const float mx = fmaxf(fmaxf(l, t), fmaxf(rr, bo));
            const float ar = (qx1 - qx0) * (qy1 - qy0);
            if ((mn > 0.f) & (mx > low) & (mx < high) && ar < best) {
                best = ar; tl = l; tt = t; tr = rr; tb = bo;
            }
        }

        if (valid) {
            float gt_iou = 0.f;
            if (best < __int_as_float(0x7f800000)) {
                const float w_i = fminf(pl, tl) + fminf(pr, tr);
                const float h_i = fminf(pt, tt) + fminf(pb, tb);
                const float a_i = fmaxf(w_i, 0.f) * fmaxf(h_i, 0.f);
                const float a_p = (pl + pr) * (pt + pb);
                const float a_t = (tl + tr) * (tt + tb);
                const float a_u = a_p + a_t - a_i + 1e-7f;
                const float iou = __fdividef(a_i, a_u);
                gt_iou = fminf(fmaxf(iou, 0.f), 1.f);
                const float w_e = fmaxf(pl, tl) + fmaxf(pr, tr);
                const float h_e = fmaxf(pt, tt) + fmaxf(pb, tb);
                const float a_e = fmaxf(w_e, 0.f) * fmaxf(h_e, 0.f) + 1e-7f;
                const float giou = iou - __fdividef(a_e - a_u, a_e);
                reg_c += 1.f - giou;
                np_c += 1.f;
            }

            // Varifocal loss, fast-math stable log-sigmoid.
            const float az = fabsf(z);
            const float e = __expf(-az);
            const float l1 = __logf(1.f + e);
            const float log_p  = fminf(z, 0.f) - l1;
            const float log_np = fminf(-z, 0.f) - l1;
            const float inv1pe = __fdividef(1.f, 1.f + e);
            const float p = (z >= 0.f ? 1.f : e) * inv1pe;
            if (gt_iou > 0.f)
                cls_c += -gt_iou * (gt_iou * log_p + (1.f - gt_iou) * log_np);
            else
                cls_c += -0.75f * p * p * log_np;
        }
    }

    // Per-warp shuffle reduction -> smem -> thread 0 writes partial slot.
    #pragma unroll
    for (int o = 16; o > 0; o >>= 1) {
        cls_c += __shfl_down_sync(FULL, cls_c, o);
        reg_c += __shfl_down_sync(FULL, reg_c, o);
        np_c  += __shfl_down_sync(FULL, np_c, o);
    }
    if (lane == 0) {
        s_red[wid]      = cls_c;
        s_red[8 + wid]  = reg_c;
        s_red[16 + wid] = np_c;
    }
    __syncthreads();
    if (tid == 0) {
        float a = 0.f, bb = 0.f, cc = 0.f;
        #pragma unroll
        for (int i = 0; i < 8; ++i) {
            a  += s_red[i];
            bb += s_red[8 + i];
            cc += s_red[16 + i];
        }
        g_p0[bid] = (double)a;
        g_p1[bid] = (double)bb;
        g_p2[bid] = (double)cc;
        __threadfence();
        const unsigned ticket = atomicAdd(&g_ticket, 1u);
        s_is_last = (ticket == (unsigned)(nblocks - 1));
    }
    __syncthreads();

    // Last-arriving block performs the deterministic final reduction.
    if (s_is_last) {
        __threadfence();  // make all partials visible
        double a = 0.0, bb = 0.0, cc = 0.0;
        for (int i = tid; i < nblocks; i += 256) {
            a  += g_p0[i];
            bb += g_p1[i];
            cc += g_p2[i];
        }
        #pragma unroll
        for (int o = 16; o > 0; o >>= 1) {
            a  += __shfl_down_sync(FULL, a, o);
            bb += __shfl_down_sync(FULL, bb, o);
            cc += __shfl_down_sync(FULL, cc, o);
        }
        if (lane == 0) {
            s_fin[wid]      = a;
            s_fin[8 + wid]  = bb;
            s_fin[16 + wid] = cc;
        }
        __syncthreads();
        if (tid == 0) {
            double fa = 0.0, fb = 0.0, fc = 0.0;
            #pragma unroll
            for (int i = 0; i < 8; ++i) {
                fa += s_fin[i];
                fb += s_fin[8 + i];
                fc += s_fin[16 + i];
            }
            const double navg = fmax(1.0, fc / (double)B);
            out[0] = (float)((fa + fb) / navg);
            out[1] = (float)(fa / navg);
            out[2] = (float)(fb / navg);
            g_ticket = 0;  // reset for next graph replay (deterministic)
        }
    }
}

extern "C" void kernel_launch(void* const* d_in, const int* in_sizes, int n_in,
                              void* d_out, int out_size) {
    const float* cls0 = (const float*)d_in[0];  // (B,1,160,160)
    const float* cls1 = (const float*)d_in[1];  // (B,1,80,80)
    const float* cls2 = (const float*)d_in[2];  // (B,1,40,40)
    const float* reg0 = (const float*)d_in[3];  // (B,4,160,160)
    const float* reg1 = (const float*)d_in[4];  // (B,4,80,80)
    const float* reg2 = (const float*)d_in[5];  // (B,4,40,40)
    const float4* gt4 = (const float4*)d_in[6]; // (B,64,4) -> 64 float4/img
    float* out = (float*)d_out;

    int B = in_sizes[6] / (64 * 4);
    if (B > MAX_B) B = MAX_B;
    const int nblocks = B * JOBS_PER_IMG;   // 1072 for B=16 -> single wave

    fcos_fused_kernel<<<nblocks, 256>>>(cls0, cls1, cls2, reg0, reg1, reg2,
                                        gt4, out, B, nblocks);
}

// round 16
// speedup vs baseline: 1.2466x; 1.0388x over previous
#include <cuda_runtime.h>

#define TILE 16
#define JOBS_PER_IMG 67     // 2 tiles per block; 134 tiles/image
#define MAX_B 64
#define NJOB_MAX (JOBS_PER_IMG * MAX_B)
#define FULL 0xffffffffu

// Per-block partial sums, contiguous arrays.
__device__ double g_p0[NJOB_MAX];
__device__ double g_p1[NJOB_MAX];
__device__ double g_p2[NJOB_MAX];
__device__ unsigned int g_ticket;   // zero-init; reset by last block each run

__global__ __launch_bounds__(256) void fcos_fused_kernel(
    const float* __restrict__ cls0, const float* __restrict__ cls1,
    const float* __restrict__ cls2,
    const float* __restrict__ reg0, const float* __restrict__ reg1,
    const float* __restrict__ reg2,
    const float4* __restrict__ gt4,
    float* __restrict__ out, int B, int nblocks)
{
    __shared__ float s_red[3 * 8];
    __shared__ double s_fin[3 * 8];
    __shared__ bool s_is_last;

    const int bid = blockIdx.x;
    const int tid = threadIdx.x;
    const int wid = tid >> 5;
    const int lane = tid & 31;
    const int b = bid / JOBS_PER_IMG;
    const int job = bid - b * JOBS_PER_IMG;

    // Each lane holds 2 boxes in registers (coalesced float4 loads).
    const float4 bxA = gt4[b * 64 + lane];
    const float4 bxB = gt4[b * 64 + 32 + lane];
    const float mwhA = fmaxf(bxA.z - bxA.x, bxA.w - bxA.y);
    const float mwhB = fmaxf(bxB.z - bxB.x, bxB.w - bxB.y);

    float cls_c = 0.f, reg_c = 0.f, np_c = 0.f;

    // Warp -> (tile, 4-row strip). Warps 0-3: tile job*2, warps 4-7: job*2+1.
    // Each thread: 2 horizontally adjacent points (float2 loads).
    {
        int r = job * 2 + (wid >> 2);   // tile id 0..133
        const int sub = wid & 3;        // 4-row strip within tile

        // Decode level + tile coords + per-level constants (warp-uniform).
        const float* cls; const float* reg;
        int H, W, tx0, ty0;
        float stride, low, high;
        if (r < 100) {
            cls = cls0; reg = reg0; H = 160; W = 160;
            stride = 4.f; low = -1.f; high = 64.f;
            ty0 = r / 10; tx0 = r - ty0 * 10;
        } else if (r < 125) {
            r -= 100;
            cls = cls1; reg = reg1; H = 80; W = 80;
            stride = 8.f; low = 64.f; high = 128.f;
            ty0 = r / 5; tx0 = r - ty0 * 5;
        } else {
            r -= 125;
            cls = cls2; reg = reg2; H = 40; W = 40;
            stride = 16.f; low = 128.f; high = 99999.f;
            ty0 = r / 3; tx0 = r - ty0 * 3;
        }

        const int w0 = tx0 * TILE;
        const int rowb = ty0 * TILE + sub * 4;   // strip rows [rowb, rowb+4)
        if (rowb < H) {                          // warp-uniform guard
            const int cw = w0 + 2 * (lane & 7);  // this thread's column pair
            const int h = rowb + (lane >> 3);    // this thread's row
            const bool valid = (cw < W) & (h < H);  // pair-aligned: cw+1<W iff cw<W

            // Warp-strip bbox over point centers.
            const float x_min = (w0 + 0.5f) * stride;
            const float x_max = ((float)min(w0 + TILE - 1, W - 1) + 0.5f) * stride;
            const float y_min = ((float)rowb + 0.5f) * stride;
            const float y_max = ((float)min(rowb + 3, H - 1) + 0.5f) * stride;

            // Candidate masks (necessary conditions: strictly-inside point has
            // max(bw,bh)/2 <= max(l,t,r,b) < max(bw,bh), plus bbox overlap).
            const bool keepA = (bxA.x < x_max) && (bxA.z > x_min) &&
                               (bxA.y < y_max) && (bxA.w > y_min) &&
                               (mwhA > low) && (0.5f * mwhA < high);
            const bool keepB = (bxB.x < x_max) && (bxB.z > x_min) &&
                               (bxB.y < y_max) && (bxB.w > y_min) &&
                               (mwhB > low) && (0.5f * mwhB < high);
            const unsigned m0 = __ballot_sync(FULL, keepA);
            const unsigned m1 = __ballot_sync(FULL, keepB);

            const float x0 = (cw + 0.5f) * stride;
            const float x1 = x0 + stride;
            const float y = (h + 0.5f) * stride;

            // Hoist the 5 float2 loads; latency overlaps the shfl scan.
            const int HW = H * W;
            const int pidx = h * W + cw;
            float2 z2 = make_float2(0.f, 0.f);
            float2 pl2 = z2, pt2 = z2, pr2 = z2, pb2 = z2;
            if (valid) {
                z2 = *(const float2*)&cls[(size_t)b * HW + pidx];
                const float* rb = reg + (size_t)b * 4 * HW + pidx;
                pl2 = *(const float2*)&rb[0];
                pt2 = *(const float2*)&rb[HW];
                pr2 = *(const float2*)&rb[2 * HW];
                pb2 = *(const float2*)&rb[3 * HW];
            }

            // Scan candidates in box-index order (LSB->MSB, chunk A then B):
            // strict < keeps the first minimum => jnp.argmin tie-breaking.
            const float INF = __int_as_float(0x7f800000);
            float best0 = INF, best1 = INF;
            float tl0 = 0.f, tt0 = 0.f, tr0 = 0.f, tb0 = 0.f;
            float tl1 = 0.f, tt1 = 0.f, tr1 = 0.f, tb1 = 0.f;

            #pragma unroll
            for (int chunk = 0; chunk < 2; ++chunk) {
                unsigned mm = chunk ? m1 : m0;
                const float4 bx = chunk ? bxB : bxA;
                while (mm) {
                    const int c = __ffs(mm) - 1; mm &= mm - 1;
                    const float qx0 = __shfl_sync(FULL, bx.x, c);
                    const float qy0 = __shfl_sync(FULL, bx.y, c);
                    const float qx1 = __shfl_sync(FULL, bx.z, c);
                    const float qy1 = __shfl_sync(FULL, bx.w, c);
                    const float t  = y - qy0;          // shared by both points
                    const float bo = qy1 - y;
                    const float tb_mn = fminf(t, bo);
                    const float tb_mx = fmaxf(t, bo);
                    const float ar = (qx1 - qx0) * (qy1 - qy0);
                    // point 0
                    const float l0  = x0 - qx0;
                    const float rr0 = qx1 - x0;
                    const float mn0 = fminf(fminf(l0, rr0), tb_mn);
                    const float mx0 = fmaxf(fmaxf(l0, rr0), tb_mx);
                    if ((mn0 > 0.f) & (mx0 > low) & (mx0 < high) && ar < best0) {
                        best0 = ar; tl0 = l0; tt0 = t; tr0 = rr0; tb0 = bo;
                    }
                    // point 1
                    const float l1  = l0 + stride;
                    const float rr1 = rr0 - stride;
                    const float mn1 = fminf(fminf(l1, rr1), tb_mn);
                    const float mx1 = fmaxf(fmaxf(l1, rr1), tb_mx);
                    if ((mn1 > 0.f) & (mx1 > low) & (mx1 < high) && ar < best1) {
                        best1 = ar; tl1 = l1; tt1 = t; tr1 = rr1; tb1 = bo;
                    }
                }
            }

            if (valid) {
                // --- point 0 regression ---
                float gt_iou0 = 0.f;
                if (best0 < INF) {
                    const float w_i = fminf(pl2.x, tl0) + fminf(pr2.x, tr0);
                    const float h_i = fminf(pt2.x, tt0) + fminf(pb2.x, tb0);
                    const float a_i = fmaxf(w_i, 0.f) * fmaxf(h_i, 0.f);
                    const float a_p = (pl2.x + pr2.x) * (pt2.x + pb2.x);
                    const float a_t = (tl0 + tr0) * (tt0 + tb0);
                    const float a_u = a_p + a_t - a_i + 1e-7f;
                    const float iou = __fdividef(a_i, a_u);
                    gt_iou0 = fminf(fmaxf(iou, 0.f), 1.f);
                    const float w_e = fmaxf(pl2.x, tl0) + fmaxf(pr2.x, tr0);
                    const float h_e = fmaxf(pt2.x, tt0) + fmaxf(pb2.x, tb0);
                    const float a_e = fmaxf(w_e, 0.f) * fmaxf(h_e, 0.f) + 1e-7f;
                    reg_c += 1.f - (iou - __fdividef(a_e - a_u, a_e));
                    np_c += 1.f;
                }
                // --- point 1 regression ---
                float gt_iou1 = 0.f;
                if (best1 < INF) {
                    const float w_i = fminf(pl2.y, tl1) + fminf(pr2.y, tr1);
                    const float h_i = fminf(pt2.y, tt1) + fminf(pb2.y, tb1);
                    const float a_i = fmaxf(w_i, 0.f) * fmaxf(h_i, 0.f);
                    const float a_p = (pl2.y + pr2.y) * (pt2.y + pb2.y);
                    const float a_t = (tl1 + tr1) * (tt1 + tb1);
                    const float a_u = a_p + a_t - a_i + 1e-7f;
                    const float iou = __fdividef(a_i, a_u);
                    gt_iou1 = fminf(fmaxf(iou, 0.f), 1.f);
                    const float w_e = fmaxf(pl2.y, tl1) + fmaxf(pr2.y, tr1);
                    const float h_e = fmaxf(pt2.y, tt1) + fmaxf(pb2.y, tb1);
                    const float a_e = fmaxf(w_e, 0.f) * fmaxf(h_e, 0.f) + 1e-7f;
                    reg_c += 1.f - (iou - __fdividef(a_e - a_u, a_e));
                    np_c += 1.f;
                }

                // --- varifocal, two independent fast-math chains (ILP) ---
                const float az0 = fabsf(z2.x);
                const float az1 = fabsf(z2.y);
                const float e0 = __expf(-az0);
                const float e1 = __expf(-az1);
                const float l10 = __logf(1.f + e0);
                const float l11 = __logf(1.f + e1);
                const float inv0 = __fdividef(1.f, 1.f + e0);
                const float inv1 = __fdividef(1.f, 1.f + e1);
                const float logp0  = fminf(z2.x, 0.f) - l10;
                const float lognp0 = fminf(-z2.x, 0.f) - l10;
                const float logp1  = fminf(z2.y, 0.f) - l11;
                const float lognp1 = fminf(-z2.y, 0.f) - l11;
                const float p0 = (z2.x >= 0.f ? 1.f : e0) * inv0;
                const float p1 = (z2.y >= 0.f ? 1.f : e1) * inv1;
                cls_c += (gt_iou0 > 0.f)
                    ? -gt_iou0 * (gt_iou0 * logp0 + (1.f - gt_iou0) * lognp0)
                    : -0.75f * p0 * p0 * lognp0;
                cls_c += (gt_iou1 > 0.f)
                    ? -gt_iou1 * (gt_iou1 * logp1 + (1.f - gt_iou1) * lognp1)
                    : -0.75f * p1 * p1 * lognp1;
            }
        }
    }

    // Per-warp shuffle reduction -> smem -> thread 0 writes partial slot.
    #pragma unroll
    for (int o = 16; o > 0; o >>= 1) {
        cls_c += __shfl_down_sync(FULL, cls_c, o);
        reg_c += __shfl_down_sync(FULL, reg_c, o);
        np_c  += __shfl_down_sync(FULL, np_c, o);
    }
    if (lane == 0) {
        s_red[wid]      = cls_c;
        s_red[8 + wid]  = reg_c;
        s_red[16 + wid] = np_c;
    }
    __syncthreads();
    if (tid == 0) {
        float a = 0.f, bb = 0.f, cc = 0.f;
        #pragma unroll
        for (int i = 0; i < 8; ++i) {
            a  += s_red[i];
            bb += s_red[8 + i];
            cc += s_red[16 + i];
        }
        g_p0[bid] = (double)a;
        g_p1[bid] = (double)bb;
        g_p2[bid] = (double)cc;
        __threadfence();
        const unsigned ticket = atomicAdd(&g_ticket, 1u);
        s_is_last = (ticket == (unsigned)(nblocks - 1));
    }
    __syncthreads();

    // Last-arriving block performs the deterministic final reduction.
    if (s_is_last) {
        __threadfence();  // make all partials visible
        double a = 0.0, bb = 0.0, cc = 0.0;
        for (int i = tid; i < nblocks; i += 256) {
            a  += g_p0[i];
            bb += g_p1[i];
            cc += g_p2[i];
        }
        #pragma unroll
        for (int o = 16; o > 0; o >>= 1) {
            a  += __shfl_down_sync(FULL, a, o);
            bb += __shfl_down_sync(FULL, bb, o);
            cc += __shfl_down_sync(FULL, cc, o);
        }
        if (lane == 0) {
            s_fin[wid]      = a;
            s_fin[8 + wid]  = bb;
            s_fin[16 + wid] = cc;
        }
        __syncthreads();
        if (tid == 0) {
            double fa = 0.0, fb = 0.0, fc = 0.0;
            #pragma unroll
            for (int i = 0; i < 8; ++i) {
                fa += s_fin[i];
                fb += s_fin[8 + i];
                fc += s_fin[16 + i];
            }
            const double navg = fmax(1.0, fc / (double)B);
            out[0] = (float)((fa + fb) / navg);
            out[1] = (float)(fa / navg);
            out[2] = (float)(fb / navg);
            g_ticket = 0;  // reset for next graph replay (deterministic)
        }
    }
}

extern "C" void kernel_launch(void* const* d_in, const int* in_sizes, int n_in,
                              void* d_out, int out_size) {
    const float* cls0 = (const float*)d_in[0];  // (B,1,160,160)
    const float* cls1 = (const float*)d_in[1];  // (B,1,80,80)
    const float* cls2 = (const float*)d_in[2];  // (B,1,40,40)
    const float* reg0 = (const float*)d_in[3];  // (B,4,160,160)
    const float* reg1 = (const float*)d_in[4];  // (B,4,80,80)
    const float* reg2 = (const float*)d_in[5];  // (B,4,40,40)
    const float4* gt4 = (const float4*)d_in[6]; // (B,64,4) -> 64 float4/img
    float* out = (float*)d_out;

    int B = in_sizes[6] / (64 * 4);
    if (B > MAX_B) B = MAX_B;
    const int nblocks = B * JOBS_PER_IMG;   // 1072 for B=16 -> single wave

    fcos_fused_kernel<<<nblocks, 256>>>(cls0, cls1, cls2, reg0, reg1, reg2,
                                        gt4, out, B, nblocks);
}